// round 7
// baseline (speedup 1.0000x reference)
#include <cuda_runtime.h>
#include <cuda_fp16.h>
#include <cuda_bf16.h>
#include <math.h>

#define D         128
#define NCOLS     256
#define MAX_NODES 100000
#define N_CTAS    782                    // ceil(100000 / 128)
#define MAX_MT    (N_CTAS * 8)           // 6256 m-tiles of 16 rows (padded)

typedef unsigned int u32;

// P (layer-1 pre-bias activations, split A|B) stored as fp16
__device__ __half g_Ph[(size_t)MAX_NODES * NCOLS];
// W1 split-bf16 in mma.sync B-fragment order:
//   ((jt*8 + kb)*32 + lane)*2 + {0,1}
__device__ u32 g_Whi[32 * 8 * 32 * 2];
__device__ u32 g_Wlo[32 * 8 * 32 * 2];
// x split-bf16 in mma.sync A-fragment order (a0..a3 per thread):
//   ((mt*8 + kb)*32 + lane)*4 + {0..3}
__device__ u32 g_Xhi[(size_t)MAX_MT * 8 * 32 * 4];
__device__ u32 g_Xlo[(size_t)MAX_MT * 8 * 32 * 4];

// ============================================================================
// helpers
// ============================================================================
__device__ __forceinline__ void mma_bf16(float* d, const u32* a, const u32* b) {
    asm volatile(
        "mma.sync.aligned.m16n8k16.row.col.f32.bf16.bf16.f32 "
        "{%0, %1, %2, %3}, {%4, %5, %6, %7}, {%8, %9}, {%0, %1, %2, %3};"
        : "+f"(d[0]), "+f"(d[1]), "+f"(d[2]), "+f"(d[3])
        : "r"(a[0]), "r"(a[1]), "r"(a[2]), "r"(a[3]), "r"(b[0]), "r"(b[1]));
}

// split fp32 pair -> bf16x2 hi word (rn) + bf16x2 residual word
__device__ __forceinline__ void split2(float f0, float f1, u32& h, u32& l) {
    __nv_bfloat162 hv = __floats2bfloat162_rn(f0, f1);   // .x=f0(lo), .y=f1(hi)
    u32 hu = *reinterpret_cast<u32*>(&hv);
    float h0 = __uint_as_float(hu << 16);
    float h1 = __uint_as_float(hu & 0xFFFF0000u);
    __nv_bfloat162 lv = __floats2bfloat162_rn(f0 - h0, f1 - h1);
    h = hu;
    l = *reinterpret_cast<u32*>(&lv);
}

// ============================================================================
// Kernel 0a: W1 -> split-bf16 B-fragments (once; 32 blocks x 256).
//   Bmat[n,k] = W1[n,k] (n<128) | W1[n-128, 128+k] (n>=128)
// ============================================================================
__global__ void prep_w_kernel(const float* __restrict__ W1)
{
    const int jt   = blockIdx.x;          // 0..31
    const int kb   = threadIdx.x >> 5;    // 0..7
    const int lane = threadIdx.x & 31;
    const int n    = jt * 8 + (lane >> 2);
    const int k0   = kb * 16 + (lane & 3) * 2;

    const float* row = (n < 128)
        ? (W1 + (size_t)n * NCOLS)
        : (W1 + (size_t)(n - 128) * NCOLS + 128);

    u32 h0, l0, h1, l1;
    split2(row[k0], row[k0 + 1], h0, l0);
    split2(row[k0 + 8], row[k0 + 9], h1, l1);

    size_t idx = (((size_t)(jt * 8 + kb)) * 32 + lane) * 2;
    g_Whi[idx] = h0;  g_Whi[idx + 1] = h1;
    g_Wlo[idx] = l0;  g_Wlo[idx + 1] = l1;
}

// ============================================================================
// Kernel 0b: x -> split-bf16 A-fragments (grid = MAX_MT blocks x 256).
// Thread (mt, kb, lane) produces fragment words a0..a3:
//   a0=(r, c2..c2+1)  a1=(r+8, c2..)  a2=(r, c2+8..)  a3=(r+8, c2+8..)
// rows beyond nN are zero-filled (padding for the last GEMM CTA).
// ============================================================================
__global__ void prep_x_kernel(const float* __restrict__ x, int nN)
{
    const int mt   = blockIdx.x;
    const int kb   = threadIdx.x >> 5;
    const int lane = threadIdx.x & 31;
    const int r    = lane >> 2;
    const int c2   = (lane & 3) * 2;
    const int m    = mt * 16 + r;
    const int k    = kb * 16 + c2;

    const float2 z = make_float2(0.f, 0.f);
    const float* p0 = x + (size_t)m * D + k;
    const float* p1 = x + (size_t)(m + 8) * D + k;
    float2 v0 = (m < nN)     ? *reinterpret_cast<const float2*>(p0)     : z;
    float2 v2 = (m < nN)     ? *reinterpret_cast<const float2*>(p0 + 8) : z;
    float2 v1 = (m + 8 < nN) ? *reinterpret_cast<const float2*>(p1)     : z;
    float2 v3 = (m + 8 < nN) ? *reinterpret_cast<const float2*>(p1 + 8) : z;

    u32 h[4], l[4];
    split2(v0.x, v0.y, h[0], l[0]);
    split2(v1.x, v1.y, h[1], l[1]);
    split2(v2.x, v2.y, h[2], l[2]);
    split2(v3.x, v3.y, h[3], l[3]);

    size_t idx = (((size_t)mt * 8 + kb) * 32 + lane) * 4;
    *reinterpret_cast<uint4*>(&g_Xhi[idx]) = make_uint4(h[0], h[1], h[2], h[3]);
    *reinterpret_cast<uint4*>(&g_Xlo[idx]) = make_uint4(l[0], l[1], l[2], l[3]);
}

// ============================================================================
// Kernel 1: P = x @ Bmat^T, split-bf16 mma.sync (3 chains), no smem,
// no conversions in the mainloop. grid = N_CTAS, block = 512
// (16 warps: 4 M-warps x 4 N-warps, warp tile 32x64).
// ============================================================================
__global__ __launch_bounds__(512, 1) void precompute_kernel(int nN)
{
    const int tid  = threadIdx.x;
    const int wid  = tid >> 5;
    const int lane = tid & 31;
    const int wm   = (wid & 3) * 32;
    const int wjt  = (wid >> 2) * 8;
    const int r    = lane >> 2;
    const int c2   = (lane & 3) * 2;
    const int m0   = blockIdx.x * 128;
    const int mtb  = blockIdx.x * 8 + (wid & 3) * 2;   // first 16-row m-tile

    float acc[2][8][4];
    #pragma unroll
    for (int i = 0; i < 2; i++)
        #pragma unroll
        for (int j = 0; j < 8; j++)
            #pragma unroll
            for (int q = 0; q < 4; q++) acc[i][j][q] = 0.f;

    #pragma unroll 2
    for (int kb = 0; kb < 8; kb++) {
        u32 ahi[2][4], alo[2][4];
        #pragma unroll
        for (int i = 0; i < 2; i++) {
            size_t aidx = (((size_t)(mtb + i) * 8 + kb) * 32 + lane) * 4;
            uint4 H = *reinterpret_cast<const uint4*>(&g_Xhi[aidx]);
            uint4 L = *reinterpret_cast<const uint4*>(&g_Xlo[aidx]);
            ahi[i][0] = H.x; ahi[i][1] = H.y; ahi[i][2] = H.z; ahi[i][3] = H.w;
            alo[i][0] = L.x; alo[i][1] = L.y; alo[i][2] = L.z; alo[i][3] = L.w;
        }

        #pragma unroll
        for (int j = 0; j < 8; j++) {
            size_t bidx = (((size_t)(wjt + j) * 8 + kb) * 32 + lane) * 2;
            uint2 bh = *reinterpret_cast<const uint2*>(&g_Whi[bidx]);
            u32 bf[2] = { bh.x, bh.y };
            mma_bf16(acc[0][j], ahi[0], bf);
            mma_bf16(acc[1][j], ahi[1], bf);
            mma_bf16(acc[0][j], alo[0], bf);
            mma_bf16(acc[1][j], alo[1], bf);
        }
        #pragma unroll
        for (int j = 0; j < 8; j++) {
            size_t bidx = (((size_t)(wjt + j) * 8 + kb) * 32 + lane) * 2;
            uint2 bl = *reinterpret_cast<const uint2*>(&g_Wlo[bidx]);
            u32 bf[2] = { bl.x, bl.y };
            mma_bf16(acc[0][j], ahi[0], bf);
            mma_bf16(acc[1][j], ahi[1], bf);
        }
    }

    // ---- epilogue: fragments -> g_Ph (fp16) ----
    #pragma unroll
    for (int i = 0; i < 2; i++) {
        #pragma unroll
        for (int j = 0; j < 8; j++) {
            const int col = (wjt + j) * 8 + c2;
            const int mA  = m0 + wm + i * 16 + r;
            if (mA < nN) {
                __half2 hv = __floats2half2_rn(acc[i][j][0], acc[i][j][1]);
                *reinterpret_cast<u32*>(&g_Ph[(size_t)mA * NCOLS + col]) =
                    *reinterpret_cast<u32*>(&hv);
            }
            const int mB = mA + 8;
            if (mB < nN) {
                __half2 hv = __floats2half2_rn(acc[i][j][2], acc[i][j][3]);
                *reinterpret_cast<u32*>(&g_Ph[(size_t)mB * NCOLS + col]) =
                    *reinterpret_cast<u32*>(&hv);
            }
        }
    }
}

// ============================================================================
// Kernel 2: per-edge MLP tail (fp16 P). One warp per 4 edges (ILP=4).
//   s = sum_j relu(A[src][j] + B[dst][j] + b1[j]) * w2[j]
//   out[e] = sigmoid(relu(s + b2))
// ============================================================================
__global__ __launch_bounds__(256) void edge_kernel(
    const void* __restrict__ edge_index,
    const float* __restrict__ b1,
    const float* __restrict__ W2,
    const float* __restrict__ b2,
    float* __restrict__ out,
    int E)
{
    const int lane   = threadIdx.x & 31;
    const int warp   = (blockIdx.x * blockDim.x + threadIdx.x) >> 5;
    const int nwarps = (gridDim.x * blockDim.x) >> 5;

    // dtype sniff: LE int64 (<2^31) => all odd 32-bit words zero
    const int* ei32 = (const int*)edge_index;
    int det = 0;
    #pragma unroll
    for (int i = 1; i < 16; i += 2) det |= __ldg(&ei32[i]);
    const bool is64 = (det == 0);
    const long long* ei64 = (const long long*)edge_index;

    const uint2* __restrict__ P2 = reinterpret_cast<const uint2*>(g_Ph);
    const float4 bias = reinterpret_cast<const float4*>(b1)[lane];
    const float4 w2   = reinterpret_cast<const float4*>(W2)[lane];
    const float  b2v  = *b2;

    for (int e = warp * 4; e < E; e += nwarps * 4) {
        int s[4], t[4];
        #pragma unroll
        for (int q = 0; q < 4; q++) {
            int eq = (e + q < E) ? (e + q) : e;
            if (is64) { s[q] = (int)ei64[eq]; t[q] = (int)ei64[E + eq]; }
            else      { s[q] = ei32[eq];      t[q] = ei32[E + eq]; }
        }

        uint2 ua[4], uc[4];
        #pragma unroll
        for (int q = 0; q < 4; q++) {
            ua[q] = P2[(size_t)s[q] * 64 + lane];
            uc[q] = P2[(size_t)t[q] * 64 + 32 + lane];
        }

        float v[4];
        #pragma unroll
        for (int q = 0; q < 4; q++) {
            float2 al = __half22float2(*reinterpret_cast<__half2*>(&ua[q].x));
            float2 ah = __half22float2(*reinterpret_cast<__half2*>(&ua[q].y));
            float2 cl = __half22float2(*reinterpret_cast<__half2*>(&uc[q].x));
            float2 ch = __half22float2(*reinterpret_cast<__half2*>(&uc[q].y));
            v[q] = fmaxf(al.x + cl.x + bias.x, 0.f) * w2.x
                 + fmaxf(al.y + cl.y + bias.y, 0.f) * w2.y
                 + fmaxf(ah.x + ch.x + bias.z, 0.f) * w2.z
                 + fmaxf(ah.y + ch.y + bias.w, 0.f) * w2.w;
        }

        #pragma unroll
        for (int o = 16; o > 0; o >>= 1) {
            #pragma unroll
            for (int q = 0; q < 4; q++)
                v[q] += __shfl_xor_sync(0xFFFFFFFFu, v[q], o);
        }

        if (lane == 0) {
            #pragma unroll
            for (int q = 0; q < 4; q++) {
                if (e + q < E) {
                    float h = fmaxf(v[q] + b2v, 0.f);
                    out[e + q] = 1.0f / (1.0f + expf(-h));
                }
            }
        }
    }
}

// ============================================================================
// Launch
// Inputs: x[f32 N*128], edge_index[2*E i32/i64], W1[f32 128*256], b1[f32 128],
//         W2[f32 128], b2[f32 1]. Output: f32 E.
// ============================================================================
extern "C" void kernel_launch(void* const* d_in, const int* in_sizes, int n_in,
                              void* d_out, int out_size)
{
    const float* x  = (const float*)d_in[0];
    const void*  ei = d_in[1];
    const float* W1 = (const float*)d_in[2];
    const float* b1 = (const float*)d_in[3];
    const float* W2 = (const float*)d_in[4];
    const float* b2 = (const float*)d_in[5];
    float*       out = (float*)d_out;

    const int N = in_sizes[0] / D;   // 100000
    const int E = in_sizes[1] / 2;   // 625000

    prep_w_kernel<<<32, 256>>>(W1);
    prep_x_kernel<<<MAX_MT, 256>>>(x, N);
    precompute_kernel<<<N_CTAS, 512>>>(N);
    edge_kernel<<<1184, 256>>>(ei, b1, W2, b2, out, E);
}

// round 8
// speedup vs baseline: 1.2869x; 1.2869x over previous
#include <cuda_runtime.h>
#include <cuda_fp16.h>
#include <math.h>

#define D         128
#define NCOLS     256
#define MAX_NODES 100000
#define N_CTAS    782                    // ceil(100000 / 128)
#define MAX_MT    (N_CTAS * 8)           // 6256 m-tiles of 16 rows (padded)

typedef unsigned int u32;

// P (layer-1 pre-bias activations, A|B halves; b1 folded into A half), fp16
__device__ __half g_Ph[(size_t)MAX_NODES * NCOLS];
// W1 as tf32 B-fragments (m16n8k8): ((jt*16 + kc)*32 + lane)*2 + {0,1}
__device__ u32 g_Wf[32 * 16 * 32 * 2];
// x as tf32 A-fragments: ((mt*16 + kc)*32 + lane)*4 + {0..3}
__device__ u32 g_Xf[(size_t)MAX_MT * 16 * 32 * 4];

// ============================================================================
// helpers
// ============================================================================
__device__ __forceinline__ u32 f2tf(float f) {
    u32 r;
    asm("cvt.rna.tf32.f32 %0, %1;" : "=r"(r) : "f"(f));
    return r;
}

__device__ __forceinline__ void mma_tf32(float* d, const u32* a, const u32* b) {
    asm volatile(
        "mma.sync.aligned.m16n8k8.row.col.f32.tf32.tf32.f32 "
        "{%0, %1, %2, %3}, {%4, %5, %6, %7}, {%8, %9}, {%0, %1, %2, %3};"
        : "+f"(d[0]), "+f"(d[1]), "+f"(d[2]), "+f"(d[3])
        : "r"(a[0]), "r"(a[1]), "r"(a[2]), "r"(a[3]), "r"(b[0]), "r"(b[1]));
}

// ============================================================================
// Kernel 0a: W1 -> tf32 B-fragments. grid=32 (jt), block=512 (kc x lane).
//   Bmat[n,k] = W1[n,k] (n<128) | W1[n-128, 128+k] (n>=128)
// Fragment (jt, kc, lane): n = jt*8 + (lane>>2), k0 = kc*8 + (lane&3)
//   b0 = Bmat[n, k0], b1 = Bmat[n, k0+4]
// ============================================================================
__global__ void prep_w_kernel(const float* __restrict__ W1)
{
    const int jt   = blockIdx.x;
    const int kc   = threadIdx.x >> 5;
    const int lane = threadIdx.x & 31;
    const int n    = jt * 8 + (lane >> 2);
    const int k0   = kc * 8 + (lane & 3);

    const float* row = (n < 128)
        ? (W1 + (size_t)n * NCOLS)
        : (W1 + (size_t)(n - 128) * NCOLS + 128);

    size_t idx = (((size_t)(jt * 16 + kc)) * 32 + lane) * 2;
    g_Wf[idx]     = f2tf(row[k0]);
    g_Wf[idx + 1] = f2tf(row[k0 + 4]);
}

// ============================================================================
// Kernel 0b: x -> tf32 A-fragments. grid=MAX_MT (mt), block=512 (kc x lane).
// Fragment (mt, kc, lane): r = lane>>2, c = lane&3
//   a0=(r, c) a1=(r+8, c) a2=(r, c+4) a3=(r+8, c+4), k base = kc*8.
// Rows >= nN zero-filled.
// ============================================================================
__global__ void prep_x_kernel(const float* __restrict__ x, int nN)
{
    const int mt   = blockIdx.x;
    const int kc   = threadIdx.x >> 5;
    const int lane = threadIdx.x & 31;
    const int r    = lane >> 2;
    const int c    = lane & 3;
    const int m    = mt * 16 + r;
    const int k    = kc * 8 + c;

    float f0 = 0.f, f1 = 0.f, f2 = 0.f, f3 = 0.f;
    if (m < nN) {
        f0 = x[(size_t)m * D + k];
        f2 = x[(size_t)m * D + k + 4];
    }
    if (m + 8 < nN) {
        f1 = x[(size_t)(m + 8) * D + k];
        f3 = x[(size_t)(m + 8) * D + k + 4];
    }

    size_t idx = (((size_t)mt * 16 + kc) * 32 + lane) * 4;
    *reinterpret_cast<uint4*>(&g_Xf[idx]) =
        make_uint4(f2tf(f0), f2tf(f1), f2tf(f2), f2tf(f3));
}

// ============================================================================
// Kernel 1: P = x @ Bmat^T (tf32 single chain). grid=N_CTAS, block=512
// (16 warps: 4 M-warps x 4 N-warps, warp tile 32x64). b1 folded into cols<128.
// ============================================================================
__global__ __launch_bounds__(512, 1) void precompute_kernel(
    const float* __restrict__ b1, int nN)
{
    const int tid  = threadIdx.x;
    const int wid  = tid >> 5;
    const int lane = tid & 31;
    const int wm   = (wid & 3) * 32;
    const int wjt  = (wid >> 2) * 8;
    const int r    = lane >> 2;
    const int c2   = (lane & 3) * 2;
    const int m0   = blockIdx.x * 128;
    const int mtb  = blockIdx.x * 8 + (wid & 3) * 2;

    float acc[2][8][4];
    #pragma unroll
    for (int i = 0; i < 2; i++)
        #pragma unroll
        for (int j = 0; j < 8; j++)
            #pragma unroll
            for (int q = 0; q < 4; q++) acc[i][j][q] = 0.f;

    #pragma unroll 4
    for (int kc = 0; kc < 16; kc++) {
        u32 a[2][4];
        #pragma unroll
        for (int i = 0; i < 2; i++) {
            size_t aidx = (((size_t)(mtb + i) * 16 + kc) * 32 + lane) * 4;
            uint4 A = *reinterpret_cast<const uint4*>(&g_Xf[aidx]);
            a[i][0] = A.x; a[i][1] = A.y; a[i][2] = A.z; a[i][3] = A.w;
        }
        #pragma unroll
        for (int j = 0; j < 8; j++) {
            size_t bidx = (((size_t)(wjt + j) * 16 + kc) * 32 + lane) * 2;
            uint2 B = *reinterpret_cast<const uint2*>(&g_Wf[bidx]);
            u32 bf[2] = { B.x, B.y };
            mma_tf32(acc[0][j], a[0], bf);
            mma_tf32(acc[1][j], a[1], bf);
        }
    }

    // ---- epilogue: + b1 (cols<128 only), fp16 store ----
    #pragma unroll
    for (int j = 0; j < 8; j++) {
        const int col = (wjt + j) * 8 + c2;
        float2 bias = make_float2(0.f, 0.f);
        if (col < 128)
            bias = *reinterpret_cast<const float2*>(b1 + col);
        #pragma unroll
        for (int i = 0; i < 2; i++) {
            const int mA = m0 + wm + i * 16 + r;
            if (mA < nN) {
                __half2 hv = __floats2half2_rn(acc[i][j][0] + bias.x,
                                               acc[i][j][1] + bias.y);
                *reinterpret_cast<u32*>(&g_Ph[(size_t)mA * NCOLS + col]) =
                    *reinterpret_cast<u32*>(&hv);
            }
            const int mB = mA + 8;
            if (mB < nN) {
                __half2 hv = __floats2half2_rn(acc[i][j][2] + bias.x,
                                               acc[i][j][3] + bias.y);
                *reinterpret_cast<u32*>(&g_Ph[(size_t)mB * NCOLS + col]) =
                    *reinterpret_cast<u32*>(&hv);
            }
        }
    }
}

// ============================================================================
// Kernel 2: per-edge MLP tail. 8 lanes per edge, 4 edge-slots per warp,
// ILP=2 (8 edges per warp iteration).
//   v = sum_j max(PA[src][j] + PB[dst][j], 0) * w2[j]    (b1 already in PA)
//   out[e] = sigmoid(relu(v + b2))
// ============================================================================
__device__ __forceinline__ float dot16(uint4 ua, uint4 uc,
                                       const float* w) {
    const __half2 z2 = __float2half2_rn(0.f);
    const __half2* a2 = reinterpret_cast<const __half2*>(&ua);
    const __half2* c2 = reinterpret_cast<const __half2*>(&uc);
    float v = 0.f;
    #pragma unroll
    for (int i = 0; i < 4; i++) {
        __half2 h = __hmax2(__hadd2(a2[i], c2[i]), z2);
        float2 f = __half22float2(h);
        v = fmaf(f.x, w[2 * i], v);
        v = fmaf(f.y, w[2 * i + 1], v);
    }
    return v;
}

__global__ __launch_bounds__(256) void edge_kernel(
    const void* __restrict__ edge_index,
    const float* __restrict__ W2,
    const float* __restrict__ b2,
    float* __restrict__ out,
    int E)
{
    const int lane   = threadIdx.x & 31;
    const int slot   = lane >> 3;          // 0..3 edge slot
    const int sub    = lane & 7;           // lane within 8-lane group
    const int warp   = (blockIdx.x * blockDim.x + threadIdx.x) >> 5;
    const int nwarps = (gridDim.x * blockDim.x) >> 5;

    // dtype sniff: LE int64 (<2^31) => all odd 32-bit words zero
    const int* ei32 = (const int*)edge_index;
    int det = 0;
    #pragma unroll
    for (int i = 1; i < 16; i += 2) det |= __ldg(&ei32[i]);
    const bool is64 = (det == 0);
    const long long* ei64 = (const long long*)edge_index;

    // per-lane w2: features [sub*8, sub*8+8) and [64+sub*8, ...)
    float w0[8], w1[8];
    {
        const float4* w4 = reinterpret_cast<const float4*>(W2);
        float4 p0 = w4[sub * 2], p1 = w4[sub * 2 + 1];
        float4 p2 = w4[16 + sub * 2], p3 = w4[16 + sub * 2 + 1];
        w0[0]=p0.x; w0[1]=p0.y; w0[2]=p0.z; w0[3]=p0.w;
        w0[4]=p1.x; w0[5]=p1.y; w0[6]=p1.z; w0[7]=p1.w;
        w1[0]=p2.x; w1[1]=p2.y; w1[2]=p2.z; w1[3]=p2.w;
        w1[4]=p3.x; w1[5]=p3.y; w1[6]=p3.z; w1[7]=p3.w;
    }
    const float b2v = *b2;
    const __half* Ph = g_Ph;

    for (int eb = warp * 8; eb < E; eb += nwarps * 8) {
        const int e0r = eb + slot;
        const int e1r = eb + 4 + slot;
        const int e0 = (e0r < E) ? e0r : (E - 1);
        const int e1 = (e1r < E) ? e1r : (E - 1);

        int s0, t0, s1, t1;
        if (is64) {
            s0 = (int)ei64[e0]; t0 = (int)ei64[E + e0];
            s1 = (int)ei64[e1]; t1 = (int)ei64[E + e1];
        } else {
            s0 = ei32[e0]; t0 = ei32[E + e0];
            s1 = ei32[e1]; t1 = ei32[E + e1];
        }

        const __half* rA0 = Ph + (size_t)s0 * NCOLS;
        const __half* rC0 = Ph + (size_t)t0 * NCOLS + 128;
        const __half* rA1 = Ph + (size_t)s1 * NCOLS;
        const __half* rC1 = Ph + (size_t)t1 * NCOLS + 128;

        uint4 a00 = *reinterpret_cast<const uint4*>(rA0 + sub * 8);
        uint4 a01 = *reinterpret_cast<const uint4*>(rA0 + 64 + sub * 8);
        uint4 c00 = *reinterpret_cast<const uint4*>(rC0 + sub * 8);
        uint4 c01 = *reinterpret_cast<const uint4*>(rC0 + 64 + sub * 8);
        uint4 a10 = *reinterpret_cast<const uint4*>(rA1 + sub * 8);
        uint4 a11 = *reinterpret_cast<const uint4*>(rA1 + 64 + sub * 8);
        uint4 c10 = *reinterpret_cast<const uint4*>(rC1 + sub * 8);
        uint4 c11 = *reinterpret_cast<const uint4*>(rC1 + 64 + sub * 8);

        float v0 = dot16(a00, c00, w0) + dot16(a01, c01, w1);
        float v1 = dot16(a10, c10, w0) + dot16(a11, c11, w1);

        // 3-level reduce within each 8-lane group
        #pragma unroll
        for (int o = 4; o > 0; o >>= 1) {
            v0 += __shfl_xor_sync(0xFFFFFFFFu, v0, o);
            v1 += __shfl_xor_sync(0xFFFFFFFFu, v1, o);
        }

        if (sub == 0) {
            if (e0r < E) {
                float h = fmaxf(v0 + b2v, 0.f);
                out[e0r] = 1.0f / (1.0f + expf(-h));
            }
            if (e1r < E) {
                float h = fmaxf(v1 + b2v, 0.f);
                out[e1r] = 1.0f / (1.0f + expf(-h));
            }
        }
    }
}

// ============================================================================
// Launch
// Inputs: x[f32 N*128], edge_index[2*E i32/i64], W1[f32 128*256], b1[f32 128],
//         W2[f32 128], b2[f32 1]. Output: f32 E.
// ============================================================================
extern "C" void kernel_launch(void* const* d_in, const int* in_sizes, int n_in,
                              void* d_out, int out_size)
{
    const float* x  = (const float*)d_in[0];
    const void*  ei = d_in[1];
    const float* W1 = (const float*)d_in[2];
    const float* b1 = (const float*)d_in[3];
    const float* W2 = (const float*)d_in[4];
    const float* b2 = (const float*)d_in[5];
    float*       out = (float*)d_out;

    const int N = in_sizes[0] / D;   // 100000
    const int E = in_sizes[1] / 2;   // 625000

    prep_w_kernel<<<32, 512>>>(W1);
    prep_x_kernel<<<MAX_MT, 512>>>(x, N);
    precompute_kernel<<<N_CTAS, 512>>>(b1, N);
    edge_kernel<<<1184, 256>>>(ei, W2, b2, out, E);
}

// round 9
// speedup vs baseline: 1.6603x; 1.2902x over previous
#include <cuda_runtime.h>
#include <cuda_fp16.h>
#include <math.h>

#define D         128
#define NCOLS     256
#define MAX_NODES 100000
#define N_CTAS    782                    // ceil(100000 / 128)

typedef unsigned int u32;

// P (layer-1 pre-bias activations, A|B halves; b1 folded into A half), fp16
__device__ __half g_Ph[(size_t)MAX_NODES * NCOLS];
// W1 as fp16 B-fragments (m16n8k16): ((jt*8 + kb)*32 + lane) -> uint2
__device__ uint2 g_Wfh[32 * 8 * 32];

// ============================================================================
// helpers
// ============================================================================
__device__ __forceinline__ u32 f2h2(float lo, float hi) {
    u32 r;
    asm("cvt.rn.f16x2.f32 %0, %1, %2;" : "=r"(r) : "f"(hi), "f"(lo));
    return r;
}

__device__ __forceinline__ void mma_f16(float* d, const u32* a, const u32* b) {
    asm volatile(
        "mma.sync.aligned.m16n8k16.row.col.f32.f16.f16.f32 "
        "{%0, %1, %2, %3}, {%4, %5, %6, %7}, {%8, %9}, {%0, %1, %2, %3};"
        : "+f"(d[0]), "+f"(d[1]), "+f"(d[2]), "+f"(d[3])
        : "r"(a[0]), "r"(a[1]), "r"(a[2]), "r"(a[3]), "r"(b[0]), "r"(b[1]));
}

// ============================================================================
// Kernel 0: W1 -> fp16 B-fragments. grid=32 (jt), block=256 (kb x lane).
//   Bmat[n,k] = W1[n,k] (n<128) | W1[n-128, 128+k] (n>=128)
// Fragment (jt, kb, lane): n = jt*8 + (lane>>2), k0 = kb*16 + (lane&3)*2
//   word0 = (Bmat[n,k0], Bmat[n,k0+1]); word1 = (Bmat[n,k0+8], Bmat[n,k0+9])
// ============================================================================
__global__ void prep_w_kernel(const float* __restrict__ W1)
{
    const int jt   = blockIdx.x;
    const int kb   = threadIdx.x >> 5;
    const int lane = threadIdx.x & 31;
    const int n    = jt * 8 + (lane >> 2);
    const int k0   = kb * 16 + (lane & 3) * 2;

    const float* row = (n < 128)
        ? (W1 + (size_t)n * NCOLS)
        : (W1 + (size_t)(n - 128) * NCOLS + 128);

    g_Wfh[(jt * 8 + kb) * 32 + lane] =
        make_uint2(f2h2(row[k0], row[k0 + 1]),
                   f2h2(row[k0 + 8], row[k0 + 9]));
}

// ============================================================================
// Kernel 1: P = x @ Bmat^T (fp16 m16n8k16, fp32 accum), x converted in-loop.
// grid = N_CTAS, block = 512 (16 warps: 4 M-warps x 4 N-warps, tile 32x64).
// b1 folded into cols < 128. P stored fp16.
// ============================================================================
__global__ __launch_bounds__(512, 1) void precompute_kernel(
    const float* __restrict__ x,
    const float* __restrict__ b1,
    int nN)
{
    const int tid  = threadIdx.x;
    const int wid  = tid >> 5;
    const int lane = tid & 31;
    const int wm   = (wid & 3) * 32;      // M offset in CTA tile
    const int wjt  = (wid >> 2) * 8;      // first n-tile of this warp
    const int r    = lane >> 2;
    const int c2   = (lane & 3) * 2;
    const int m0   = blockIdx.x * 128;

    float acc[2][8][4];
    #pragma unroll
    for (int i = 0; i < 2; i++)
        #pragma unroll
        for (int j = 0; j < 8; j++)
            #pragma unroll
            for (int q = 0; q < 4; q++) acc[i][j][q] = 0.f;

    const float2 z = make_float2(0.f, 0.f);

    #pragma unroll
    for (int kb = 0; kb < 8; kb++) {
        const int k = kb * 16 + c2;

        // A fragments: load fp32 pairs, convert to fp16x2 in registers
        u32 a[2][4];
        #pragma unroll
        for (int i = 0; i < 2; i++) {
            const int mA = m0 + wm + i * 16 + r;
            const int mB = mA + 8;
            const float* pA = x + (size_t)mA * D + k;
            const float* pB = x + (size_t)mB * D + k;
            float2 v0 = (mA < nN) ? *reinterpret_cast<const float2*>(pA)     : z;
            float2 v2 = (mA < nN) ? *reinterpret_cast<const float2*>(pA + 8) : z;
            float2 v1 = (mB < nN) ? *reinterpret_cast<const float2*>(pB)     : z;
            float2 v3 = (mB < nN) ? *reinterpret_cast<const float2*>(pB + 8) : z;
            a[i][0] = f2h2(v0.x, v0.y);
            a[i][1] = f2h2(v1.x, v1.y);
            a[i][2] = f2h2(v2.x, v2.y);
            a[i][3] = f2h2(v3.x, v3.y);
        }

        #pragma unroll
        for (int j = 0; j < 8; j++) {
            uint2 B = g_Wfh[((wjt + j) * 8 + kb) * 32 + lane];
            u32 bf[2] = { B.x, B.y };
            mma_f16(acc[0][j], a[0], bf);
            mma_f16(acc[1][j], a[1], bf);
        }
    }

    // ---- epilogue: + b1 (cols<128 only), fp16 store ----
    #pragma unroll
    for (int j = 0; j < 8; j++) {
        const int col = (wjt + j) * 8 + c2;
        float2 bias = make_float2(0.f, 0.f);
        if (col < 128)
            bias = *reinterpret_cast<const float2*>(b1 + col);
        #pragma unroll
        for (int i = 0; i < 2; i++) {
            const int mA = m0 + wm + i * 16 + r;
            if (mA < nN) {
                *reinterpret_cast<u32*>(&g_Ph[(size_t)mA * NCOLS + col]) =
                    f2h2(acc[i][j][0] + bias.x, acc[i][j][1] + bias.y);
            }
            const int mB = mA + 8;
            if (mB < nN) {
                *reinterpret_cast<u32*>(&g_Ph[(size_t)mB * NCOLS + col]) =
                    f2h2(acc[i][j][2] + bias.x, acc[i][j][3] + bias.y);
            }
        }
    }
}

// ============================================================================
// Kernel 2: per-edge MLP tail. 8 lanes per edge, 4 edge-slots per warp,
// ILP=2 (8 edges per warp iteration).
//   v = sum_j max(PA[src][j] + PB[dst][j], 0) * w2[j]    (b1 already in PA)
//   out[e] = sigmoid(relu(v + b2))
// ============================================================================
__device__ __forceinline__ float dot16(uint4 ua, uint4 uc, const float* w) {
    const __half2 z2 = __float2half2_rn(0.f);
    const __half2* a2 = reinterpret_cast<const __half2*>(&ua);
    const __half2* c2 = reinterpret_cast<const __half2*>(&uc);
    float v = 0.f;
    #pragma unroll
    for (int i = 0; i < 4; i++) {
        __half2 h = __hmax2(__hadd2(a2[i], c2[i]), z2);
        float2 f = __half22float2(h);
        v = fmaf(f.x, w[2 * i], v);
        v = fmaf(f.y, w[2 * i + 1], v);
    }
    return v;
}

__global__ __launch_bounds__(256) void edge_kernel(
    const void* __restrict__ edge_index,
    const float* __restrict__ W2,
    const float* __restrict__ b2,
    float* __restrict__ out,
    int E)
{
    const int lane   = threadIdx.x & 31;
    const int slot   = lane >> 3;
    const int sub    = lane & 7;
    const int warp   = (blockIdx.x * blockDim.x + threadIdx.x) >> 5;
    const int nwarps = (gridDim.x * blockDim.x) >> 5;

    // dtype sniff: LE int64 (<2^31) => all odd 32-bit words zero
    const int* ei32 = (const int*)edge_index;
    int det = 0;
    #pragma unroll
    for (int i = 1; i < 16; i += 2) det |= __ldg(&ei32[i]);
    const bool is64 = (det == 0);
    const long long* ei64 = (const long long*)edge_index;

    float w0[8], w1[8];
    {
        const float4* w4 = reinterpret_cast<const float4*>(W2);
        float4 p0 = w4[sub * 2], p1 = w4[sub * 2 + 1];
        float4 p2 = w4[16 + sub * 2], p3 = w4[16 + sub * 2 + 1];
        w0[0]=p0.x; w0[1]=p0.y; w0[2]=p0.z; w0[3]=p0.w;
        w0[4]=p1.x; w0[5]=p1.y; w0[6]=p1.z; w0[7]=p1.w;
        w1[0]=p2.x; w1[1]=p2.y; w1[2]=p2.z; w1[3]=p2.w;
        w1[4]=p3.x; w1[5]=p3.y; w1[6]=p3.z; w1[7]=p3.w;
    }
    const float b2v = *b2;
    const __half* Ph = g_Ph;

    for (int eb = warp * 8; eb < E; eb += nwarps * 8) {
        const int e0r = eb + slot;
        const int e1r = eb + 4 + slot;
        const int e0 = (e0r < E) ? e0r : (E - 1);
        const int e1 = (e1r < E) ? e1r : (E - 1);

        int s0, t0, s1, t1;
        if (is64) {
            s0 = (int)ei64[e0]; t0 = (int)ei64[E + e0];
            s1 = (int)ei64[e1]; t1 = (int)ei64[E + e1];
        } else {
            s0 = ei32[e0]; t0 = ei32[E + e0];
            s1 = ei32[e1]; t1 = ei32[E + e1];
        }

        const __half* rA0 = Ph + (size_t)s0 * NCOLS;
        const __half* rC0 = Ph + (size_t)t0 * NCOLS + 128;
        const __half* rA1 = Ph + (size_t)s1 * NCOLS;
        const __half* rC1 = Ph + (size_t)t1 * NCOLS + 128;

        uint4 a00 = *reinterpret_cast<const uint4*>(rA0 + sub * 8);
        uint4 a01 = *reinterpret_cast<const uint4*>(rA0 + 64 + sub * 8);
        uint4 c00 = *reinterpret_cast<const uint4*>(rC0 + sub * 8);
        uint4 c01 = *reinterpret_cast<const uint4*>(rC0 + 64 + sub * 8);
        uint4 a10 = *reinterpret_cast<const uint4*>(rA1 + sub * 8);
        uint4 a11 = *reinterpret_cast<const uint4*>(rA1 + 64 + sub * 8);
        uint4 c10 = *reinterpret_cast<const uint4*>(rC1 + sub * 8);
        uint4 c11 = *reinterpret_cast<const uint4*>(rC1 + 64 + sub * 8);

        float v0 = dot16(a00, c00, w0) + dot16(a01, c01, w1);
        float v1 = dot16(a10, c10, w0) + dot16(a11, c11, w1);

        #pragma unroll
        for (int o = 4; o > 0; o >>= 1) {
            v0 += __shfl_xor_sync(0xFFFFFFFFu, v0, o);
            v1 += __shfl_xor_sync(0xFFFFFFFFu, v1, o);
        }

        if (sub == 0) {
            if (e0r < E) {
                float h = fmaxf(v0 + b2v, 0.f);
                out[e0r] = 1.0f / (1.0f + expf(-h));
            }
            if (e1r < E) {
                float h = fmaxf(v1 + b2v, 0.f);
                out[e1r] = 1.0f / (1.0f + expf(-h));
            }
        }
    }
}

// ============================================================================
// Launch
// Inputs: x[f32 N*128], edge_index[2*E i32/i64], W1[f32 128*256], b1[f32 128],
//         W2[f32 128], b2[f32 1]. Output: f32 E.
// ============================================================================
extern "C" void kernel_launch(void* const* d_in, const int* in_sizes, int n_in,
                              void* d_out, int out_size)
{
    const float* x  = (const float*)d_in[0];
    const void*  ei = d_in[1];
    const float* W1 = (const float*)d_in[2];
    const float* b1 = (const float*)d_in[3];
    const float* W2 = (const float*)d_in[4];
    const float* b2 = (const float*)d_in[5];
    float*       out = (float*)d_out;

    const int N = in_sizes[0] / D;   // 100000
    const int E = in_sizes[1] / 2;   // 625000

    prep_w_kernel<<<32, 256>>>(W1);
    precompute_kernel<<<N_CTAS, 512>>>(x, b1, N);
    edge_kernel<<<1184, 256>>>(ei, W2, b2, out, E);
}

// round 10
// speedup vs baseline: 2.0410x; 1.2293x over previous
#include <cuda_runtime.h>
#include <cuda_fp16.h>
#include <math.h>

#define D         128
#define NCOLS     256
#define MAX_NODES 100000
#define N_CTAS    1563                   // ceil(100000 / 64)
#define MAX_MT    (N_CTAS * 4)           // 6252 m-tiles of 16 rows (padded)

typedef unsigned int u32;

// P (layer-1 pre-bias activations, A|B halves; b1 folded into A half), fp16
__device__ __half g_Ph[(size_t)MAX_NODES * NCOLS];
// W1 as paired fp16 B-fragments: ((jp*8 + kb)*32 + lane) -> uint4
//   {n-tile 2jp word0, word1, n-tile 2jp+1 word0, word1}
__device__ uint4 g_W4[16 * 8 * 32];
// x as fp16 A-fragments: ((mt*8 + kb)*32 + lane) -> uint4 {a0,a1,a2,a3}
__device__ uint4 g_X4[(size_t)MAX_MT * 8 * 32];

// ============================================================================
// helpers
// ============================================================================
__device__ __forceinline__ u32 f2h2(float lo, float hi) {
    u32 r;
    asm("cvt.rn.f16x2.f32 %0, %1, %2;" : "=r"(r) : "f"(hi), "f"(lo));
    return r;
}

__device__ __forceinline__ void mma_f16(float* d, const u32* a, u32 b0, u32 b1) {
    asm volatile(
        "mma.sync.aligned.m16n8k16.row.col.f32.f16.f16.f32 "
        "{%0, %1, %2, %3}, {%4, %5, %6, %7}, {%8, %9}, {%0, %1, %2, %3};"
        : "+f"(d[0]), "+f"(d[1]), "+f"(d[2]), "+f"(d[3])
        : "r"(a[0]), "r"(a[1]), "r"(a[2]), "r"(a[3]), "r"(b0), "r"(b1));
}

// ============================================================================
// Kernel 0a: W1 -> paired fp16 B-fragments. grid=16 (jp), block=256 (kb,lane).
//   Bmat[n,k] = W1[n,k] (n<128) | W1[n-128, 128+k] (n>=128)
// For n-tile j: n = j*8 + (lane>>2), k0 = kb*16 + (lane&3)*2,
//   word0 = (Bmat[n,k0], Bmat[n,k0+1]); word1 = (Bmat[n,k0+8], Bmat[n,k0+9])
// ============================================================================
__global__ void prep_w_kernel(const float* __restrict__ W1)
{
    const int jp   = blockIdx.x;          // n-tile pair 0..15
    const int kb   = threadIdx.x >> 5;
    const int lane = threadIdx.x & 31;
    const int n0   = jp * 16 + (lane >> 2);      // n-tile 2jp
    const int n1   = n0 + 8;                     // n-tile 2jp+1
    const int k0   = kb * 16 + (lane & 3) * 2;

    const float* r0 = (n0 < 128) ? (W1 + (size_t)n0 * NCOLS)
                                 : (W1 + (size_t)(n0 - 128) * NCOLS + 128);
    const float* r1 = (n1 < 128) ? (W1 + (size_t)n1 * NCOLS)
                                 : (W1 + (size_t)(n1 - 128) * NCOLS + 128);

    g_W4[(jp * 8 + kb) * 32 + lane] =
        make_uint4(f2h2(r0[k0], r0[k0 + 1]), f2h2(r0[k0 + 8], r0[k0 + 9]),
                   f2h2(r1[k0], r1[k0 + 1]), f2h2(r1[k0 + 8], r1[k0 + 9]));
}

// ============================================================================
// Kernel 0b: x -> fp16 A-fragments. grid=MAX_MT (mt), block=256 (kb,lane).
//   r = lane>>2, c2 = (lane&3)*2, k = kb*16+c2, m = mt*16+r
//   a0=(m,k..k+1) a1=(m+8,k..) a2=(m,k+8..) a3=(m+8,k+8..); OOB rows -> 0
// ============================================================================
__global__ void prep_x_kernel(const float* __restrict__ x, int nN)
{
    const int mt   = blockIdx.x;
    const int kb   = threadIdx.x >> 5;
    const int lane = threadIdx.x & 31;
    const int r    = lane >> 2;
    const int k    = kb * 16 + (lane & 3) * 2;
    const int m    = mt * 16 + r;

    const float2 z = make_float2(0.f, 0.f);
    const float* p0 = x + (size_t)m * D + k;
    const float* p1 = x + (size_t)(m + 8) * D + k;
    float2 v0 = (m < nN)     ? *reinterpret_cast<const float2*>(p0)     : z;
    float2 v2 = (m < nN)     ? *reinterpret_cast<const float2*>(p0 + 8) : z;
    float2 v1 = (m + 8 < nN) ? *reinterpret_cast<const float2*>(p1)     : z;
    float2 v3 = (m + 8 < nN) ? *reinterpret_cast<const float2*>(p1 + 8) : z;

    g_X4[((size_t)mt * 8 + kb) * 32 + lane] =
        make_uint4(f2h2(v0.x, v0.y), f2h2(v1.x, v1.y),
                   f2h2(v2.x, v2.y), f2h2(v3.x, v3.y));
}

// ============================================================================
// Kernel 1: P = x @ Bmat^T (fp16 m16n8k16, fp32 accum), pure fragment loads.
// grid = N_CTAS (64 rows each), block = 256 (8 warps: 2 M-warps x 4 N-warps,
// warp tile 32x64). b1 folded into cols < 128. P stored fp16.
// ============================================================================
__global__ __launch_bounds__(256, 2) void precompute_kernel(
    const float* __restrict__ b1, int nN)
{
    const int tid  = threadIdx.x;
    const int wid  = tid >> 5;
    const int lane = tid & 31;
    const int wmg  = wid & 1;             // M-warp group (2)
    const int wng  = wid >> 1;            // N-warp group (4)
    const int wm   = wmg * 32;
    const int wjt  = wng * 8;             // first n-tile
    const int r    = lane >> 2;
    const int c2   = (lane & 3) * 2;
    const int m0   = blockIdx.x * 64;
    const int mtb  = blockIdx.x * 4 + wmg * 2;

    float acc[2][8][4];
    #pragma unroll
    for (int i = 0; i < 2; i++)
        #pragma unroll
        for (int j = 0; j < 8; j++)
            #pragma unroll
            for (int q = 0; q < 4; q++) acc[i][j][q] = 0.f;

    #pragma unroll
    for (int kb = 0; kb < 8; kb++) {
        u32 a[2][4];
        #pragma unroll
        for (int i = 0; i < 2; i++) {
            uint4 A = g_X4[((size_t)(mtb + i) * 8 + kb) * 32 + lane];
            a[i][0] = A.x; a[i][1] = A.y; a[i][2] = A.z; a[i][3] = A.w;
        }
        #pragma unroll
        for (int jp = 0; jp < 4; jp++) {
            uint4 B = g_W4[(((wjt >> 1) + jp) * 8 + kb) * 32 + lane];
            mma_f16(acc[0][2 * jp],     a[0], B.x, B.y);
            mma_f16(acc[1][2 * jp],     a[1], B.x, B.y);
            mma_f16(acc[0][2 * jp + 1], a[0], B.z, B.w);
            mma_f16(acc[1][2 * jp + 1], a[1], B.z, B.w);
        }
    }

    // ---- epilogue: + b1 (cols<128 only), fp16 store ----
    #pragma unroll
    for (int j = 0; j < 8; j++) {
        const int col = (wjt + j) * 8 + c2;
        float2 bias = make_float2(0.f, 0.f);
        if (col < 128)
            bias = *reinterpret_cast<const float2*>(b1 + col);
        #pragma unroll
        for (int i = 0; i < 2; i++) {
            const int mA = m0 + wm + i * 16 + r;
            if (mA < nN) {
                *reinterpret_cast<u32*>(&g_Ph[(size_t)mA * NCOLS + col]) =
                    f2h2(acc[i][j][0] + bias.x, acc[i][j][1] + bias.y);
            }
            const int mB = mA + 8;
            if (mB < nN) {
                *reinterpret_cast<u32*>(&g_Ph[(size_t)mB * NCOLS + col]) =
                    f2h2(acc[i][j][2] + bias.x, acc[i][j][3] + bias.y);
            }
        }
    }
}

// ============================================================================
// Kernel 2: per-edge MLP tail. 8 lanes per edge, 4 edge-slots per warp,
// ILP=2 (8 edges per warp iteration).
//   v = sum_j max(PA[src][j] + PB[dst][j], 0) * w2[j]    (b1 already in PA)
//   out[e] = sigmoid(relu(v + b2))
// ============================================================================
__device__ __forceinline__ float dot16(uint4 ua, uint4 uc, const float* w) {
    const __half2 z2 = __float2half2_rn(0.f);
    const __half2* a2 = reinterpret_cast<const __half2*>(&ua);
    const __half2* c2 = reinterpret_cast<const __half2*>(&uc);
    float v = 0.f;
    #pragma unroll
    for (int i = 0; i < 4; i++) {
        __half2 h = __hmax2(__hadd2(a2[i], c2[i]), z2);
        float2 f = __half22float2(h);
        v = fmaf(f.x, w[2 * i], v);
        v = fmaf(f.y, w[2 * i + 1], v);
    }
    return v;
}

__global__ __launch_bounds__(256) void edge_kernel(
    const void* __restrict__ edge_index,
    const float* __restrict__ W2,
    const float* __restrict__ b2,
    float* __restrict__ out,
    int E)
{
    const int lane   = threadIdx.x & 31;
    const int slot   = lane >> 3;
    const int sub    = lane & 7;
    const int warp   = (blockIdx.x * blockDim.x + threadIdx.x) >> 5;
    const int nwarps = (gridDim.x * blockDim.x) >> 5;

    // dtype sniff: LE int64 (<2^31) => all odd 32-bit words zero
    const int* ei32 = (const int*)edge_index;
    int det = 0;
    #pragma unroll
    for (int i = 1; i < 16; i += 2) det |= __ldg(&ei32[i]);
    const bool is64 = (det == 0);
    const long long* ei64 = (const long long*)edge_index;

    float w0[8], w1[8];
    {
        const float4* w4 = reinterpret_cast<const float4*>(W2);
        float4 p0 = w4[sub * 2], p1 = w4[sub * 2 + 1];
        float4 p2 = w4[16 + sub * 2], p3 = w4[16 + sub * 2 + 1];
        w0[0]=p0.x; w0[1]=p0.y; w0[2]=p0.z; w0[3]=p0.w;
        w0[4]=p1.x; w0[5]=p1.y; w0[6]=p1.z; w0[7]=p1.w;
        w1[0]=p2.x; w1[1]=p2.y; w1[2]=p2.z; w1[3]=p2.w;
        w1[4]=p3.x; w1[5]=p3.y; w1[6]=p3.z; w1[7]=p3.w;
    }
    const float b2v = *b2;
    const __half* Ph = g_Ph;

    for (int eb = warp * 8; eb < E; eb += nwarps * 8) {
        const int e0r = eb + slot;
        const int e1r = eb + 4 + slot;
        const int e0 = (e0r < E) ? e0r : (E - 1);
        const int e1 = (e1r < E) ? e1r : (E - 1);

        int s0, t0, s1, t1;
        if (is64) {
            s0 = (int)ei64[e0]; t0 = (int)ei64[E + e0];
            s1 = (int)ei64[e1]; t1 = (int)ei64[E + e1];
        } else {
            s0 = ei32[e0]; t0 = ei32[E + e0];
            s1 = ei32[e1]; t1 = ei32[E + e1];
        }

        const __half* rA0 = Ph + (size_t)s0 * NCOLS;
        const __half* rC0 = Ph + (size_t)t0 * NCOLS + 128;
        const __half* rA1 = Ph + (size_t)s1 * NCOLS;
        const __half* rC1 = Ph + (size_t)t1 * NCOLS + 128;

        uint4 a00 = *reinterpret_cast<const uint4*>(rA0 + sub * 8);
        uint4 a01 = *reinterpret_cast<const uint4*>(rA0 + 64 + sub * 8);
        uint4 c00 = *reinterpret_cast<const uint4*>(rC0 + sub * 8);
        uint4 c01 = *reinterpret_cast<const uint4*>(rC0 + 64 + sub * 8);
        uint4 a10 = *reinterpret_cast<const uint4*>(rA1 + sub * 8);
        uint4 a11 = *reinterpret_cast<const uint4*>(rA1 + 64 + sub * 8);
        uint4 c10 = *reinterpret_cast<const uint4*>(rC1 + sub * 8);
        uint4 c11 = *reinterpret_cast<const uint4*>(rC1 + 64 + sub * 8);

        float v0 = dot16(a00, c00, w0) + dot16(a01, c01, w1);
        float v1 = dot16(a10, c10, w0) + dot16(a11, c11, w1);

        #pragma unroll
        for (int o = 4; o > 0; o >>= 1) {
            v0 += __shfl_xor_sync(0xFFFFFFFFu, v0, o);
            v1 += __shfl_xor_sync(0xFFFFFFFFu, v1, o);
        }

        if (sub == 0) {
            if (e0r < E) {
                float h = fmaxf(v0 + b2v, 0.f);
                out[e0r] = 1.0f / (1.0f + expf(-h));
            }
            if (e1r < E) {
                float h = fmaxf(v1 + b2v, 0.f);
                out[e1r] = 1.0f / (1.0f + expf(-h));
            }
        }
    }
}

// ============================================================================
// Launch
// Inputs: x[f32 N*128], edge_index[2*E i32/i64], W1[f32 128*256], b1[f32 128],
//         W2[f32 128], b2[f32 1]. Output: f32 E.
// ============================================================================
extern "C" void kernel_launch(void* const* d_in, const int* in_sizes, int n_in,
                              void* d_out, int out_size)
{
    const float* x  = (const float*)d_in[0];
    const void*  ei = d_in[1];
    const float* W1 = (const float*)d_in[2];
    const float* b1 = (const float*)d_in[3];
    const float* W2 = (const float*)d_in[4];
    const float* b2 = (const float*)d_in[5];
    float*       out = (float*)d_out;

    const int N = in_sizes[0] / D;   // 100000
    const int E = in_sizes[1] / 2;   // 625000

    prep_w_kernel<<<16, 256>>>(W1);
    prep_x_kernel<<<MAX_MT, 256>>>(x, N);
    precompute_kernel<<<N_CTAS, 256>>>(b1, N);
    edge_kernel<<<1184, 256>>>(ei, W2, b2, out, E);
}